// round 16
// baseline (speedup 1.0000x reference)
#include <cuda_runtime.h>
#include <math.h>

#define BB 8
#define NN 512
#define DD 128
#define HH 128

// scratch (no allocation allowed in kernel_launch)
__device__ float g_xw[BB * NN * DD];   // x @ gcn_w
__device__ float g_dinv[BB * NN];      // rsqrt(deg)

// ---------------------------------------------------------------------------
// Main adjacency kernel: for block (j-tile, b*N+i) compute
//   score[j] = b2 + sum_h relu( sum_d |x_i[d]-x_j[d]| * W1[d][h] + b1[h] ) * w2[h]
//   adj[b][i][j] = sigmoid(score[j])
// Block = 256 threads as 16(tx:h) x 16(ty:j), 8x8 register micro-tile.
// ---------------------------------------------------------------------------
__global__ __launch_bounds__(256, 2)
void adj_kernel(const float* __restrict__ x,  const float* __restrict__ w1,
                const float* __restrict__ b1, const float* __restrict__ w2,
                const float* __restrict__ b2, float* __restrict__ adj)
{
    __shared__ float xis[DD];
    __shared__ float W1s[32][128];
    __shared__ float ds[32][132];   // |xi - xj| transposed [k][j], pad->16B aligned rows

    const int bi  = blockIdx.y;          // b*N + i
    const int b   = bi / NN;
    const int i   = bi % NN;
    const int j0  = blockIdx.x * 128;
    const int tid = threadIdx.x;
    const int tx  = tid & 15;            // h-group
    const int ty  = tid >> 4;            // j-group

    if (tid < 32) {
        float4 v = *(const float4*)&x[((long)(b * NN + i)) * DD + tid * 4];
        *(float4*)&xis[tid * 4] = v;
    }

    float acc[8][8];
    float w2r[8];
#pragma unroll
    for (int n = 0; n < 8; n++) {
        float bb = b1[tx * 8 + n];
        w2r[n]   = w2[tx * 8 + n];
#pragma unroll
        for (int m = 0; m < 8; m++) acc[m][n] = bb;
    }
    __syncthreads();

    for (int kb = 0; kb < DD; kb += 32) {
        // stage W1 chunk [32][128] (coalesced float4)
#pragma unroll
        for (int it = 0; it < 4; it++) {
            int e  = tid + it * 256;           // 1024 float4s
            int r  = e >> 5;
            int c4 = e & 31;
            *(float4*)&W1s[r][c4 * 4] =
                *(const float4*)&w1[(kb + r) * HH + c4 * 4];
        }
        // stage |xi - xj| chunk, transposed to [k][j]
#pragma unroll
        for (int it = 0; it < 4; it++) {
            int e  = tid + it * 256;
            int j  = e >> 3;                   // 0..127
            int kq = e & 7;                    // float4 within 32-k chunk
            float4 v = *(const float4*)&x[((long)(b * NN + j0 + j)) * DD + kb + kq * 4];
            ds[kq * 4 + 0][j] = fabsf(xis[kb + kq * 4 + 0] - v.x);
            ds[kq * 4 + 1][j] = fabsf(xis[kb + kq * 4 + 1] - v.y);
            ds[kq * 4 + 2][j] = fabsf(xis[kb + kq * 4 + 2] - v.z);
            ds[kq * 4 + 3][j] = fabsf(xis[kb + kq * 4 + 3] - v.w);
        }
        __syncthreads();

#pragma unroll
        for (int k = 0; k < 32; k++) {
            float4 a0 = *(float4*)&ds[k][ty * 8];
            float4 a1 = *(float4*)&ds[k][ty * 8 + 4];
            float4 c0 = *(float4*)&W1s[k][tx * 8];
            float4 c1 = *(float4*)&W1s[k][tx * 8 + 4];
            float av[8] = {a0.x, a0.y, a0.z, a0.w, a1.x, a1.y, a1.z, a1.w};
            float bv[8] = {c0.x, c0.y, c0.z, c0.w, c1.x, c1.y, c1.z, c1.w};
#pragma unroll
            for (int m = 0; m < 8; m++)
#pragma unroll
                for (int n = 0; n < 8; n++)
                    acc[m][n] = fmaf(av[m], bv[n], acc[m][n]);
        }
        __syncthreads();
    }

    // epilogue: relu, dot with w2 over this thread's 8 h, reduce across 16 tx lanes
    const float base = b2[0];
#pragma unroll
    for (int m = 0; m < 8; m++) {
        float s = 0.f;
#pragma unroll
        for (int n = 0; n < 8; n++)
            s += fmaxf(acc[m][n], 0.f) * w2r[n];
#pragma unroll
        for (int off = 8; off; off >>= 1)
            s += __shfl_xor_sync(0xffffffffu, s, off, 16);
        if (tx == 0) {
            float sc = s + base;
            float a  = 1.f / (1.f + expf(-sc));
            adj[((long)(b * NN + i)) * NN + j0 + ty * 8 + m] = a;
        }
    }
}

// ---------------------------------------------------------------------------
// deg[row] = sum_j adj[row][j];  g_dinv = rsqrt(deg).  1 warp per row.
// ---------------------------------------------------------------------------
__global__ void deg_kernel(const float* __restrict__ adj)
{
    int row  = blockIdx.x * 8 + (threadIdx.x >> 5);
    int lane = threadIdx.x & 31;
    const float* r = adj + (long)row * NN;
    float s = 0.f;
#pragma unroll 4
    for (int j = lane; j < NN; j += 32) s += r[j];
#pragma unroll
    for (int off = 16; off; off >>= 1)
        s += __shfl_xor_sync(0xffffffffu, s, off);
    if (lane == 0) g_dinv[row] = rsqrtf(s);
}

// ---------------------------------------------------------------------------
// g_xw[row][o] = sum_d x[row][d] * gcn_w[d][o]. 1 block per row, thread = o.
// ---------------------------------------------------------------------------
__global__ void xw_kernel(const float* __restrict__ x, const float* __restrict__ gw)
{
    int row = blockIdx.x;
    int o   = threadIdx.x;
    __shared__ float xr[DD];
    if (threadIdx.x < 32)
        *(float4*)&xr[threadIdx.x * 4] =
            *(const float4*)&x[(long)row * DD + threadIdx.x * 4];
    __syncthreads();
    float s = 0.f;
#pragma unroll 8
    for (int d = 0; d < DD; d++)
        s = fmaf(xr[d], gw[d * DD + o], s);
    g_xw[(long)row * DD + o] = s;
}

// ---------------------------------------------------------------------------
// out[b][i][o] = dinv[i] * sum_j adj[i][j]*dinv[j]*xw[j][o] + gcn_b[o]
// Block handles 4 consecutive i rows (amortizes xw traffic). thread = o.
// ---------------------------------------------------------------------------
__global__ void out_kernel(const float* __restrict__ adj,
                           const float* __restrict__ gcn_b,
                           float* __restrict__ out)
{
    int b  = blockIdx.y;
    int i0 = blockIdx.x * 4;
    int o  = threadIdx.x;

    __shared__ float arow[4][NN];
    __shared__ float dj[NN];

    for (int j = threadIdx.x; j < NN; j += 128) dj[j] = g_dinv[b * NN + j];
#pragma unroll
    for (int r = 0; r < 4; r++)
        for (int j = threadIdx.x; j < NN; j += 128)
            arow[r][j] = adj[((long)(b * NN + i0 + r)) * NN + j];
    __syncthreads();

    float a0 = 0.f, a1 = 0.f, a2 = 0.f, a3 = 0.f;
#pragma unroll 4
    for (int j = 0; j < NN; j++) {
        float xv = g_xw[((long)(b * NN + j)) * DD + o];
        float w  = dj[j];
        a0 = fmaf(arow[0][j] * w, xv, a0);
        a1 = fmaf(arow[1][j] * w, xv, a1);
        a2 = fmaf(arow[2][j] * w, xv, a2);
        a3 = fmaf(arow[3][j] * w, xv, a3);
    }
    float gb = gcn_b[o];
    out[((long)(b * NN + i0 + 0)) * DD + o] = g_dinv[b * NN + i0 + 0] * a0 + gb;
    out[((long)(b * NN + i0 + 1)) * DD + o] = g_dinv[b * NN + i0 + 1] * a1 + gb;
    out[((long)(b * NN + i0 + 2)) * DD + o] = g_dinv[b * NN + i0 + 2] * a2 + gb;
    out[((long)(b * NN + i0 + 3)) * DD + o] = g_dinv[b * NN + i0 + 3] * a3 + gb;
}

// ---------------------------------------------------------------------------
extern "C" void kernel_launch(void* const* d_in, const int* in_sizes, int n_in,
                              void* d_out, int out_size)
{
    const float* x     = (const float*)d_in[0];  // [8,512,128]
    const float* w1    = (const float*)d_in[1];  // [128,128]
    const float* b1    = (const float*)d_in[2];  // [128]
    const float* w2    = (const float*)d_in[3];  // [128]
    const float* b2    = (const float*)d_in[4];  // [1]
    const float* gcn_w = (const float*)d_in[5];  // [128,128]
    const float* gcn_b = (const float*)d_in[6];  // [128]

    float* out_ptr = (float*)d_out;                       // [8,512,128]
    float* adj_ptr = (float*)d_out + (long)BB * NN * DD;  // [8,512,512]

    adj_kernel<<<dim3(NN / 128, BB * NN), 256>>>(x, w1, b1, w2, b2, adj_ptr);
    deg_kernel<<<BB * NN / 8, 256>>>(adj_ptr);
    xw_kernel<<<BB * NN, 128>>>(x, gcn_w);
    out_kernel<<<dim3(NN / 4, BB), 128>>>(adj_ptr, gcn_b, out_ptr);
}